// round 8
// baseline (speedup 1.0000x reference)
#include <cuda_runtime.h>
#include <cuda_fp16.h>

#define N_NODES 100000
#define N_EDGES 3200000
#define N_QUADS (N_EDGES / 4)   // 4 edges per thread (best measured config)

// ---------------- scratch (device globals; no allocation allowed) ----------
__device__ float   g_deg[N_NODES];   // zeroed by cudaMemsetAsync; self-loop +1 folded into prescale
__device__ float   g_dinv[N_NODES];
__device__ __half2 g_y[N_NODES];     // f16x2(dinv[n] * x[n])   layer-1 source msgs
__device__ float2  g_agg1[N_NODES];  // (A+I) @ y               f32 accumulation
__device__ __half2 g_zs[N_NODES];    // f16x2(dinv[n] * z[n])   layer-2 source msgs

// Vector f32x2 reduction to global (PTX 8.1+, sm_90+). Halves atomic op count.
__device__ __forceinline__ void red_add_v2(float2* addr, float a, float b) {
    asm volatile("red.global.add.v2.f32 [%0], {%1, %2};"
                 :: "l"(addr), "f"(a), "f"(b) : "memory");
}

// K2: degree accumulation at destinations. 4 edges per thread via int4.
__global__ void k_degree(const int* __restrict__ dst) {
    int i = blockIdx.x * blockDim.x + threadIdx.x;
    if (i < N_QUADS) {
        int4 d = reinterpret_cast<const int4*>(dst)[i];
        atomicAdd(&g_deg[d.x], 1.0f);
        atomicAdd(&g_deg[d.y], 1.0f);
        atomicAdd(&g_deg[d.z], 1.0f);
        atomicAdd(&g_deg[d.w], 1.0f);
    }
}

// K3: dinv = rsqrt(deg+1); y = dinv*x stored f16x2; agg1 init with f32 self-loop.
__global__ void k_prescale(const float* __restrict__ x) {
    int n = blockIdx.x * blockDim.x + threadIdx.x;
    if (n < N_NODES) {
        float di = rsqrtf(g_deg[n] + 1.0f);   // +1 = self-loop
        g_dinv[n] = di;
        float2 xv = reinterpret_cast<const float2*>(x)[n];
        float2 y  = make_float2(di * xv.x, di * xv.y);
        g_y[n]    = __floats2half2_rn(y.x, y.y);
        g_agg1[n] = y;                        // self-loop in full precision
    }
}

// K4: layer-1 aggregation: agg1[d] += y[s].
__global__ void k_agg1(const int* __restrict__ src,
                       const int* __restrict__ dst) {
    int i = blockIdx.x * blockDim.x + threadIdx.x;
    if (i < N_QUADS) {
        int4 s = reinterpret_cast<const int4*>(src)[i];
        int4 d = reinterpret_cast<const int4*>(dst)[i];
        float2 y0 = __half22float2(g_y[s.x]);
        float2 y1 = __half22float2(g_y[s.y]);
        float2 y2 = __half22float2(g_y[s.z]);
        float2 y3 = __half22float2(g_y[s.w]);
        red_add_v2(&g_agg1[d.x], y0.x, y0.y);
        red_add_v2(&g_agg1[d.y], y1.x, y1.y);
        red_add_v2(&g_agg1[d.z], y2.x, y2.y);
        red_add_v2(&g_agg1[d.w], y3.x, y3.y);
    }
}

// K5: per-node fused dense chain, 2 THREADS PER NODE (even: j 0-31, odd: j 32-63).
//   Doubles grid parallelism (occ cap 33% -> 66%) and halves the serial FMA chain.
//   Partials combined with one shfl_xor(1); even lane writes.
__global__ void k_node(const float* __restrict__ W1,
                       const float* __restrict__ b1,
                       const float* __restrict__ W2,
                       float2* __restrict__ out) {
    __shared__ float4 sWp[64];   // {W1[j][0], W1[j][1], W2[0][j], W2[1][j]}
    __shared__ float  sb1[64];
    int t = threadIdx.x;
    if (t < 64) {
        sWp[t] = make_float4(W1[2 * t], W1[2 * t + 1], W2[t], W2[64 + t]);
        sb1[t] = b1[t];
    }
    __syncthreads();

    int gt   = blockIdx.x * blockDim.x + t;
    int n    = gt >> 1;            // node index
    int half = gt & 1;             // which 32 of the 64 hidden units
    bool valid = (n < N_NODES);
    int nc  = valid ? n : 0;       // clamped for safe loads

    float  di = g_dinv[nc];
    float2 ag = g_agg1[nc];
    float  ax = di * ag.x, ay = di * ag.y;

    float zx = 0.0f, zy = 0.0f;
    int jb = half << 5;
#pragma unroll
    for (int k = 0; k < 32; k++) {
        int j = jb + k;
        float4 w = sWp[j];
        float h = fmaf(w.x, ax, fmaf(w.y, ay, sb1[j]));
        h = fmaxf(h, 0.0f);
        zx = fmaf(w.z, h, zx);
        zy = fmaf(w.w, h, zy);
    }
    // combine partner partials (lanes 2k / 2k+1 hold the two halves of node n)
    zx += __shfl_xor_sync(0xFFFFFFFFu, zx, 1);
    zy += __shfl_xor_sync(0xFFFFFFFFu, zy, 1);

    if (valid && half == 0) {
        float zsx = di * zx, zsy = di * zy;
        g_zs[n] = __floats2half2_rn(zsx, zsy);
        out[n]  = make_float2(zsx, zsy);      // self-loop in full precision
    }
}

// K6: layer-2 aggregation directly into d_out: out[d] += zs[s].
__global__ void k_agg2(const int* __restrict__ src,
                       const int* __restrict__ dst,
                       float2* __restrict__ out) {
    int i = blockIdx.x * blockDim.x + threadIdx.x;
    if (i < N_QUADS) {
        int4 s = reinterpret_cast<const int4*>(src)[i];
        int4 d = reinterpret_cast<const int4*>(dst)[i];
        float2 z0 = __half22float2(g_zs[s.x]);
        float2 z1 = __half22float2(g_zs[s.y]);
        float2 z2 = __half22float2(g_zs[s.z]);
        float2 z3 = __half22float2(g_zs[s.w]);
        red_add_v2(&out[d.x], z0.x, z0.y);
        red_add_v2(&out[d.y], z1.x, z1.y);
        red_add_v2(&out[d.z], z2.x, z2.y);
        red_add_v2(&out[d.w], z3.x, z3.y);
    }
}

// K7: destination post-scale + bias: out[n] = dinv[n]*out[n] + b2.
__global__ void k_final(const float* __restrict__ b2,
                        float2* __restrict__ out) {
    int n = blockIdx.x * blockDim.x + threadIdx.x;
    if (n < N_NODES) {
        float di = g_dinv[n];
        float2 o = out[n];
        float bb0 = __ldg(&b2[0]), bb1 = __ldg(&b2[1]);
        out[n] = make_float2(fmaf(di, o.x, bb0), fmaf(di, o.y, bb1));
    }
}

extern "C" void kernel_launch(void* const* d_in, const int* in_sizes, int n_in,
                              void* d_out, int out_size) {
    const float* x  = (const float*)d_in[0];
    const int*   ei = (const int*)d_in[1];
    const float* W1 = (const float*)d_in[2];
    const float* b1 = (const float*)d_in[3];
    const float* W2 = (const float*)d_in[4];
    const float* b2 = (const float*)d_in[5];
    float2*      out = (float2*)d_out;

    const int* src = ei;
    const int* dst = ei + N_EDGES;

    const int TB = 256;
    int nb_nodes = (N_NODES + TB - 1) / TB;
    int nb_node2 = (2 * N_NODES + TB - 1) / TB;   // 2 threads per node
    int nb_quads = (N_QUADS + TB - 1) / TB;

    // Zero degree buffer (capturable; not an allocation). Self-loop +1 folded
    // into k_prescale.
    void* deg_ptr = nullptr;
    cudaGetSymbolAddress(&deg_ptr, g_deg);
    cudaMemsetAsync(deg_ptr, 0, N_NODES * sizeof(float));

    k_degree  <<<nb_quads, TB>>>(dst);
    k_prescale<<<nb_nodes, TB>>>(x);
    k_agg1    <<<nb_quads, TB>>>(src, dst);
    k_node    <<<nb_node2, TB>>>(W1, b1, W2, out);
    k_agg2    <<<nb_quads, TB>>>(src, dst, out);
    k_final   <<<nb_nodes, TB>>>(b2, out);
}

// round 9
// speedup vs baseline: 1.0008x; 1.0008x over previous
#include <cuda_runtime.h>
#include <cuda_fp16.h>

#define N_NODES 100000
#define N_EDGES 3200000
#define N_QUADS (N_EDGES / 4)   // 4 edges per thread (best measured config)

// ---------------- scratch (device globals; no allocation allowed) ----------
__device__ float   g_deg[N_NODES];   // zeroed by cudaMemsetAsync; self-loop +1 folded into prescale
__device__ float   g_dinv[N_NODES];
__device__ __half2 g_y[N_NODES];     // f16x2(dinv[n] * x[n])   layer-1 source msgs
__device__ float2  g_agg1[N_NODES];  // (A+I) @ y               f32 accumulation
__device__ __half2 g_zs[N_NODES];    // f16x2(dinv[n] * z[n])   layer-2 source msgs

// Vector f32x2 reduction to global (PTX 8.1+, sm_90+). Halves atomic op count.
__device__ __forceinline__ void red_add_v2(float2* addr, float a, float b) {
    asm volatile("red.global.add.v2.f32 [%0], {%1, %2};"
                 :: "l"(addr), "f"(a), "f"(b) : "memory");
}

// K2: degree accumulation at destinations. 4 edges per thread via int4.
__global__ void k_degree(const int* __restrict__ dst) {
    int i = blockIdx.x * blockDim.x + threadIdx.x;
    if (i < N_QUADS) {
        int4 d = reinterpret_cast<const int4*>(dst)[i];
        atomicAdd(&g_deg[d.x], 1.0f);
        atomicAdd(&g_deg[d.y], 1.0f);
        atomicAdd(&g_deg[d.z], 1.0f);
        atomicAdd(&g_deg[d.w], 1.0f);
    }
}

// K3: dinv = rsqrt(deg+1); y = dinv*x stored f16x2; agg1 init with f32 self-loop.
__global__ void k_prescale(const float* __restrict__ x) {
    int n = blockIdx.x * blockDim.x + threadIdx.x;
    if (n < N_NODES) {
        float di = rsqrtf(g_deg[n] + 1.0f);   // +1 = self-loop
        g_dinv[n] = di;
        float2 xv = reinterpret_cast<const float2*>(x)[n];
        float2 y  = make_float2(di * xv.x, di * xv.y);
        g_y[n]    = __floats2half2_rn(y.x, y.y);
        g_agg1[n] = y;                        // self-loop in full precision
    }
}

// K4: layer-1 aggregation: agg1[d] += y[s].
__global__ void k_agg1(const int* __restrict__ src,
                       const int* __restrict__ dst) {
    int i = blockIdx.x * blockDim.x + threadIdx.x;
    if (i < N_QUADS) {
        int4 s = reinterpret_cast<const int4*>(src)[i];
        int4 d = reinterpret_cast<const int4*>(dst)[i];
        float2 y0 = __half22float2(g_y[s.x]);
        float2 y1 = __half22float2(g_y[s.y]);
        float2 y2 = __half22float2(g_y[s.z]);
        float2 y3 = __half22float2(g_y[s.w]);
        red_add_v2(&g_agg1[d.x], y0.x, y0.y);
        red_add_v2(&g_agg1[d.y], y1.x, y1.y);
        red_add_v2(&g_agg1[d.z], y2.x, y2.y);
        red_add_v2(&g_agg1[d.w], y3.x, y3.y);
    }
}

// K5: per-node fused dense chain. 1 thread/node, packed float4 weights,
//     4 independent accumulator pairs to break the serial FMA chain (ILP).
__global__ void k_node(const float* __restrict__ W1,
                       const float* __restrict__ b1,
                       const float* __restrict__ W2,
                       float2* __restrict__ out) {
    __shared__ float4 sWp[64];   // {W1[j][0], W1[j][1], W2[0][j], W2[1][j]}
    __shared__ float  sb1[64];
    int t = threadIdx.x;
    if (t < 64) {
        sWp[t] = make_float4(W1[2 * t], W1[2 * t + 1], W2[t], W2[64 + t]);
        sb1[t] = b1[t];
    }
    __syncthreads();

    int n = blockIdx.x * blockDim.x + t;
    if (n >= N_NODES) return;

    float  di = g_dinv[n];
    float2 ag = g_agg1[n];
    float  ax = di * ag.x, ay = di * ag.y;

    float zx0 = 0.f, zx1 = 0.f, zx2 = 0.f, zx3 = 0.f;
    float zy0 = 0.f, zy1 = 0.f, zy2 = 0.f, zy3 = 0.f;
#pragma unroll
    for (int k = 0; k < 16; k++) {
        int j = 4 * k;
        float4 w0 = sWp[j],     w1 = sWp[j + 1];
        float4 w2 = sWp[j + 2], w3 = sWp[j + 3];
        float h0 = fmaxf(fmaf(w0.x, ax, fmaf(w0.y, ay, sb1[j])),     0.f);
        float h1 = fmaxf(fmaf(w1.x, ax, fmaf(w1.y, ay, sb1[j + 1])), 0.f);
        float h2 = fmaxf(fmaf(w2.x, ax, fmaf(w2.y, ay, sb1[j + 2])), 0.f);
        float h3 = fmaxf(fmaf(w3.x, ax, fmaf(w3.y, ay, sb1[j + 3])), 0.f);
        zx0 = fmaf(w0.z, h0, zx0);  zy0 = fmaf(w0.w, h0, zy0);
        zx1 = fmaf(w1.z, h1, zx1);  zy1 = fmaf(w1.w, h1, zy1);
        zx2 = fmaf(w2.z, h2, zx2);  zy2 = fmaf(w2.w, h2, zy2);
        zx3 = fmaf(w3.z, h3, zx3);  zy3 = fmaf(w3.w, h3, zy3);
    }
    float zx = (zx0 + zx1) + (zx2 + zx3);
    float zy = (zy0 + zy1) + (zy2 + zy3);

    float zsx = di * zx, zsy = di * zy;
    g_zs[n] = __floats2half2_rn(zsx, zsy);
    out[n]  = make_float2(zsx, zsy);          // self-loop in full precision
}

// K6: layer-2 aggregation directly into d_out: out[d] += zs[s].
__global__ void k_agg2(const int* __restrict__ src,
                       const int* __restrict__ dst,
                       float2* __restrict__ out) {
    int i = blockIdx.x * blockDim.x + threadIdx.x;
    if (i < N_QUADS) {
        int4 s = reinterpret_cast<const int4*>(src)[i];
        int4 d = reinterpret_cast<const int4*>(dst)[i];
        float2 z0 = __half22float2(g_zs[s.x]);
        float2 z1 = __half22float2(g_zs[s.y]);
        float2 z2 = __half22float2(g_zs[s.z]);
        float2 z3 = __half22float2(g_zs[s.w]);
        red_add_v2(&out[d.x], z0.x, z0.y);
        red_add_v2(&out[d.y], z1.x, z1.y);
        red_add_v2(&out[d.z], z2.x, z2.y);
        red_add_v2(&out[d.w], z3.x, z3.y);
    }
}

// K7: destination post-scale + bias: out[n] = dinv[n]*out[n] + b2.
__global__ void k_final(const float* __restrict__ b2,
                        float2* __restrict__ out) {
    int n = blockIdx.x * blockDim.x + threadIdx.x;
    if (n < N_NODES) {
        float di = g_dinv[n];
        float2 o = out[n];
        float bb0 = __ldg(&b2[0]), bb1 = __ldg(&b2[1]);
        out[n] = make_float2(fmaf(di, o.x, bb0), fmaf(di, o.y, bb1));
    }
}

extern "C" void kernel_launch(void* const* d_in, const int* in_sizes, int n_in,
                              void* d_out, int out_size) {
    const float* x  = (const float*)d_in[0];
    const int*   ei = (const int*)d_in[1];
    const float* W1 = (const float*)d_in[2];
    const float* b1 = (const float*)d_in[3];
    const float* W2 = (const float*)d_in[4];
    const float* b2 = (const float*)d_in[5];
    float2*      out = (float2*)d_out;

    const int* src = ei;
    const int* dst = ei + N_EDGES;

    const int TB = 256;
    int nb_nodes = (N_NODES + TB - 1) / TB;
    int nb_quads = (N_QUADS + TB - 1) / TB;

    // Zero degree buffer (capturable; not an allocation). Self-loop +1 folded
    // into k_prescale.
    void* deg_ptr = nullptr;
    cudaGetSymbolAddress(&deg_ptr, g_deg);
    cudaMemsetAsync(deg_ptr, 0, N_NODES * sizeof(float));

    k_degree  <<<nb_quads, TB>>>(dst);
    k_prescale<<<nb_nodes, TB>>>(x);
    k_agg1    <<<nb_quads, TB>>>(src, dst);
    k_node    <<<nb_nodes, TB>>>(W1, b1, W2, out);
    k_agg2    <<<nb_quads, TB>>>(src, dst, out);
    k_final   <<<nb_nodes, TB>>>(b2, out);
}